// round 7
// baseline (speedup 1.0000x reference)
#include <cuda_runtime.h>
#include <cuda_bf16.h>
#include <math_constants.h>
#include <limits.h>

// Segment-max pooling with sorted segment ids (N rows x 32 ch -> M segments).
// One warp owns CHUNK=64 rows; lane = channel. Boundary rows precomputed as a
// 64-bit ballot mask. Skip-start: rows before the warp's first boundary are
// read by the previous warp's tail scan -- skipped entirely here. All i0
// comparisons are warp-uniform BRANCHES (not per-lane selects): only the one
// partial batch per chunk pays the masked-load cost. Tail ids prefetched.

#define CHUNK 64
#define BATCH 8

typedef unsigned long long ull;

__global__ __launch_bounds__(256, 8) void seg_max_kernel(
    const float* __restrict__ feat,
    const int*   __restrict__ ids,
    float*       __restrict__ out,
    int N, int M)
{
    const unsigned FULL = 0xFFFFFFFFu;
    const int lane = threadIdx.x & 31;
    const int warp = blockIdx.x * (blockDim.x >> 5) + (threadIdx.x >> 5);

    const long long r0 = (long long)warp * CHUNK;
    if (r0 >= N) return;
    const int nrows = (int)(((long long)N - r0 < CHUNK) ? (N - r0) : CHUNK);

    // Coalesced load of this chunk's segment ids (2 x 32 lanes).
    int id_lo = (lane < nrows)      ? ids[r0 + lane]      : 0;
    int id_hi = (32 + lane < nrows) ? ids[r0 + 32 + lane] : 0;
    // Prefetch the 32 ids after the chunk (tail scan input), issued early.
    int idn0  = (r0 + CHUNK + lane < N) ? ids[r0 + CHUNK + lane] : INT_MAX;

    const int prev_id = (r0 > 0) ? ids[r0 - 1] : -1;

    int   cur  = prev_id;
    bool  resp = false;
    float m    = -CUDART_INF_F;

    const float* fptr = feat + r0 * 32 + lane;

    if (nrows == CHUNK) {
        // 64-bit boundary mask: bit i set iff ids[r0+i] != ids[r0+i-1].
        int p = __shfl_up_sync(FULL, id_lo, 1);
        if (lane == 0) p = prev_id;
        unsigned mlo = __ballot_sync(FULL, id_lo != p);

        int s = __shfl_sync(FULL, id_lo, 31);
        p = __shfl_up_sync(FULL, id_hi, 1);
        if (lane == 0) p = s;
        unsigned mhi = __ballot_sync(FULL, id_hi != p);

        const ull bmask = (ull)mlo | ((ull)mhi << 32);
        // First row we own; rows before it belong to the previous warp.
        const int i0 = bmask ? (__ffsll((long long)bmask) - 1) : CHUNK;

        #pragma unroll
        for (int base = 0; base < CHUNK; base += BATCH) {
            if (base + BATCH <= i0) continue;     // uniform: fully skipped

            float v[BATCH];
            if (base >= i0) {
                // uniform: fully owned -- clean unconditional LDG stream
                #pragma unroll
                for (int j = 0; j < BATCH; ++j)
                    v[j] = __ldcs(&fptr[(base + j) * 32]);
            } else {
                // uniform: the single partial batch in this chunk
                #pragma unroll
                for (int j = 0; j < BATCH; ++j)
                    v[j] = (base + j >= i0) ? __ldcs(&fptr[(base + j) * 32])
                                            : -CUDART_INF_F;
            }

            const unsigned bb = (unsigned)(bmask >> base) & 0xFFu;
            if (bb == 0u) {                       // uniform: no boundary
                float a = fmaxf(v[0], v[1]);
                float b = fmaxf(v[2], v[3]);
                float c = fmaxf(v[4], v[5]);
                float d = fmaxf(v[6], v[7]);
                m = fmaxf(m, fmaxf(fmaxf(a, b), fmaxf(c, d)));
            } else {
                #pragma unroll
                for (int j = 0; j < BATCH; ++j) {
                    if ((bb >> j) & 1u) {         // uniform (mask bit)
                        const int i = base + j;
                        int nid = __shfl_sync(FULL, (i < 32) ? id_lo : id_hi,
                                              i & 31);
                        if (resp) {
                            out[(long long)cur * 32 + lane] = m;
                            for (int g = cur + 1; g < nid; ++g)
                                out[(long long)g * 32 + lane] = 0.0f;
                        }
                        cur  = nid;
                        m    = -CUDART_INF_F;
                        resp = true;
                    }
                    m = fmaxf(m, v[j]);
                }
            }
        }
    } else {
        // Ragged last chunk: scalar path (one warp in the grid).
        for (int i = 0; i < nrows; ++i) {
            int id = __shfl_sync(FULL, (i < 32) ? id_lo : id_hi, i & 31);
            if (id != cur) {
                if (resp) {
                    out[(long long)cur * 32 + lane] = m;
                    for (int g = cur + 1; g < id; ++g)
                        out[(long long)g * 32 + lane] = 0.0f;
                }
                cur  = id;
                m    = -CUDART_INF_F;
                resp = true;
            }
            m = fmaxf(m, fptr[(long long)i * 32]);
        }
    }

    // Finish the last segment we own: it may continue past the chunk end.
    long long r = r0 + nrows;
    if (resp) {
        bool first = (nrows == CHUNK);
        while (r < N) {                       // uniform condition
            long long rl = r + lane;
            int idn = first ? idn0
                            : ((rl < N) ? ids[rl] : INT_MAX);
            first = false;
            unsigned diff = __ballot_sync(FULL, idn != cur);
            int k = diff ? (__ffs(diff) - 1) : 32;      // continuation rows
            for (int j = 0; j < k; ++j)                 // independent loads
                m = fmaxf(m, __ldcs(&feat[(r + j) * 32 + lane]));
            r += k;
            if (k < 32) break;
        }
        out[(long long)cur * 32 + lane] = m;
        int next_id = (r < N) ? ids[r] : M;
        for (int g = cur + 1; g < next_id; ++g)
            out[(long long)g * 32 + lane] = 0.0f;
    }

    // Leading gap: segments before ids[0] are empty.
    if (r0 == 0) {
        int first_id = ids[0];
        for (int g = 0; g < first_id; ++g)
            out[(long long)g * 32 + lane] = 0.0f;
    }
}

extern "C" void kernel_launch(void* const* d_in, const int* in_sizes, int n_in,
                              void* d_out, int out_size) {
    const float* feat = (const float*)d_in[0];
    const int*   ids  = (const int*)d_in[1];
    float*       out  = (float*)d_out;

    const int N = in_sizes[1];
    const int M = out_size / 32;

    const int warps   = (N + CHUNK - 1) / CHUNK;
    const int threads = 256;
    const int blocks  = (warps * 32 + threads - 1) / threads;

    seg_max_kernel<<<blocks, threads>>>(feat, ids, out, N, M);
}